// round 1
// baseline (speedup 1.0000x reference)
#include <cuda_runtime.h>
#include <math.h>

#define NB 8
#define NL 512
#define NCH 16
#define NE 128
#define NHID 128
#define NT1 129
#define NT2 513

// ---------------- device scratch ----------------
__device__ float g_key_e[NB*NL*NE];
__device__ float g_clsq [128*NE];
__device__ float g_Qb   [NB*NL*NE];
__device__ float g_Kb   [NB*NL*NE];
__device__ float g_Qc   [128*NE];
__device__ float g_o32a [NB*NL*32];
__device__ float g_o32c [NB*128*32];
__device__ float g_Xh   [NB*NT1*NHID];
__device__ float g_Xh2  [NB*NT2*NHID];
__device__ float g_bq   [NB*NT2*NHID];
__device__ float g_bk   [NB*NT2*NHID];
__device__ float g_bv   [NB*NT2*NHID];
__device__ float g_bao  [NB*NT2*NHID];
__device__ float g_bx2  [NB*NT2*NHID];
__device__ float g_hout [NB*NT1*NHID];

// ---------------- time embedding ----------------
__global__ void emb_kernel(const float* __restrict__ ts,
                           const float* __restrict__ w_per, const float* __restrict__ b_per,
                           const float* __restrict__ w_lin, const float* __restrict__ b_lin)
{
    int row = blockIdx.x, j = threadIdx.x;
    float t; float* dst;
    if (row < NB*NL) { t = ts[row]; dst = g_key_e + (size_t)row*NE; }
    else             { int i = row - NB*NL; t = (float)i * (1.0f/127.0f); dst = g_clsq + (size_t)i*NE; }
    float v;
    if (j == 0) v = t*w_lin[0] + b_lin[0];
    else        v = sinf(t*w_per[j-1] + b_per[j-1]);
    dst[j] = v;
}

// ---------------- SGEMM: C[M x 128] = A[M x 128] @ W[128 x 128] + bias (opt relu) ----
__global__ void gemm128_kernel(const float* __restrict__ A, const float* __restrict__ W,
                               const float* __restrict__ bias, float* __restrict__ C,
                               int M, int relu)
{
    __shared__ float As[16][64];
    __shared__ float Ws[16][64];
    const int tid = threadIdx.x;            // 256 threads
    const int tn = tid & 15, tm = tid >> 4;
    const int m0 = blockIdx.x * 64, n0 = blockIdx.y * 64;
    float acc[4][4];
    #pragma unroll
    for (int i=0;i<4;i++)
        #pragma unroll
        for (int j=0;j<4;j++) acc[i][j] = 0.f;

    const int la  = tid * 4;
    const int lar = la >> 4, lac = la & 15;   // A tile: 64 rows x 16 cols
    const int lwr = la >> 6, lwc = la & 63;   // W tile: 16 rows x 64 cols

    for (int kk = 0; kk < 128; kk += 16) {
        float4 av = make_float4(0.f,0.f,0.f,0.f);
        int gm = m0 + lar;
        if (gm < M) av = *(const float4*)(A + (size_t)gm*128 + kk + lac);
        float4 wv = *(const float4*)(W + (size_t)(kk+lwr)*128 + n0 + lwc);
        __syncthreads();
        As[lac+0][lar]=av.x; As[lac+1][lar]=av.y; As[lac+2][lar]=av.z; As[lac+3][lar]=av.w;
        *(float4*)&Ws[lwr][lwc] = wv;
        __syncthreads();
        #pragma unroll
        for (int k=0;k<16;k++) {
            float a[4], b[4];
            *(float4*)a = *(const float4*)&As[k][tm*4];
            *(float4*)b = *(const float4*)&Ws[k][tn*4];
            #pragma unroll
            for (int i=0;i<4;i++)
                #pragma unroll
                for (int j=0;j<4;j++) acc[i][j] = fmaf(a[i], b[j], acc[i][j]);
        }
    }
    float4 bv4 = *(const float4*)(bias + n0 + tn*4);
    float bb[4] = {bv4.x, bv4.y, bv4.z, bv4.w};
    #pragma unroll
    for (int i=0;i<4;i++) {
        int gm = m0 + tm*4 + i;
        if (gm < M) {
            float4 o;
            o.x = acc[i][0]+bb[0]; o.y = acc[i][1]+bb[1];
            o.z = acc[i][2]+bb[2]; o.w = acc[i][3]+bb[3];
            if (relu) { o.x=fmaxf(o.x,0.f); o.y=fmaxf(o.y,0.f); o.z=fmaxf(o.z,0.f); o.w=fmaxf(o.w,0.f); }
            *(float4*)(C + (size_t)gm*128 + n0 + tn*4) = o;
        }
    }
}

// ---------------- masked per-channel attention (mTA) ----------------
// block: 128 threads; 64 q rows (2 threads/q, key halves), grid (Lq/64, B*H)
__global__ void mta_kernel(const float* __restrict__ Q, int qStride, int Lq,
                           const float* __restrict__ K, const float* __restrict__ X,
                           float* __restrict__ o32)
{
    const int bh = blockIdx.y, b = bh >> 1, h = bh & 1;
    const int tid = threadIdx.x, lane = tid & 31, warp = tid >> 5;
    const int qi = blockIdx.x*64 + warp*16 + (lane & 15);
    const int half = lane >> 4;
    __shared__ float sK[2][32][64];
    __shared__ float sX[2][32][16];

    float4 qreg[16];
    const float* qp = Q + (size_t)b*qStride + (size_t)qi*128 + h*64;
    #pragma unroll
    for (int i=0;i<16;i++) qreg[i] = *(const float4*)(qp + i*4);

    float m = -1e30f;
    float den[8], num[8];
    #pragma unroll
    for (int c=0;c<8;c++){ den[c]=0.f; num[c]=0.f; }

    for (int c=0;c<8;c++) {             // 8 chunks of 32 keys per half
        __syncthreads();
        #pragma unroll
        for (int u=0;u<8;u++) {
            int e = (tid*8+u)*4;
            int hh = e>>11, kk = (e>>6)&31, d = e&63;
            int kglob = hh*256 + c*32 + kk;
            *(float4*)&sK[hh][kk][d] =
                *(const float4*)(K + ((size_t)b*NL + kglob)*128 + h*64 + d);
        }
        #pragma unroll
        for (int u=0;u<2;u++) {
            int e = (tid*2+u)*4;
            int hh = e>>9, kk = (e>>4)&31, d = e&15;
            int kglob = hh*256 + c*32 + kk;
            *(float4*)&sX[hh][kk][d] =
                *(const float4*)(X + ((size_t)b*NL + kglob)*16 + d);
        }
        __syncthreads();
        for (int kk=0;kk<32;kk++) {
            const float4* kr = (const float4*)sK[half][kk];
            float4 a4 = make_float4(0.f,0.f,0.f,0.f);
            #pragma unroll
            for (int i=0;i<16;i++) {
                float4 kv = kr[i];
                a4.x = fmaf(kv.x, qreg[i].x, a4.x);
                a4.y = fmaf(kv.y, qreg[i].y, a4.y);
                a4.z = fmaf(kv.z, qreg[i].z, a4.z);
                a4.w = fmaf(kv.w, qreg[i].w, a4.w);
            }
            float s = ((a4.x+a4.y)+(a4.z+a4.w))*0.125f;
            if (s > m) {
                float f = __expf(m - s);
                #pragma unroll
                for (int cc=0;cc<8;cc++){ den[cc]*=f; num[cc]*=f; }
                m = s;
            }
            float e = __expf(s - m);
            const float* xr = sX[half][kk];
            #pragma unroll
            for (int cc=0;cc<8;cc++) {
                float t = e * xr[8+cc];
                den[cc] += t;
                num[cc] = fmaf(t, xr[cc], num[cc]);
            }
        }
    }
    // merge the two key-halves (partner = lane ^ 16)
    float m2 = __shfl_xor_sync(0xffffffffu, m, 16);
    float Mx = fmaxf(m, m2);
    float f1 = __expf(m - Mx), f2 = __expf(m2 - Mx);
    #pragma unroll
    for (int cc=0;cc<8;cc++) {
        float d2 = __shfl_xor_sync(0xffffffffu, den[cc], 16);
        float n2 = __shfl_xor_sync(0xffffffffu, num[cc], 16);
        den[cc] = den[cc]*f1 + d2*f2;
        num[cc] = num[cc]*f1 + n2*f2;
    }
    if (half == 0) {
        float res[16];
        #pragma unroll
        for (int cc=0;cc<8;cc++) {
            bool ok = den[cc] > 0.f;
            res[cc]   = ok ? num[cc]/den[cc] : 0.f;
            res[8+cc] = ok ? 1.f : 0.f;
        }
        float* dst = o32 + ((size_t)b*Lq + qi)*32 + h*16;
        #pragma unroll
        for (int i=0;i<4;i++)
            *(float4*)(dst + i*4) = make_float4(res[i*4],res[i*4+1],res[i*4+2],res[i*4+3]);
    }
}

// ---------------- 32->128 projection (Wo_t) into token slot 1+q ----------------
__global__ void proj32_kernel(const float* __restrict__ A, const float* __restrict__ W,
                              const float* __restrict__ bias, float* __restrict__ out,
                              int M, int Lq, int Tper, const float* __restrict__ pos)
{
    __shared__ float sW[32*128];
    __shared__ float sA[32*32];
    const int r0 = blockIdx.x * 32;
    for (int i = threadIdx.x; i < 4096; i += 256) sW[i] = W[i];
    for (int i = threadIdx.x; i < 1024; i += 256) {
        int r = r0 + (i >> 5);
        sA[i] = (r < M) ? A[(size_t)r*32 + (i & 31)] : 0.f;
    }
    __syncthreads();
    #pragma unroll
    for (int u=0;u<16;u++) {
        int oi = threadIdx.x + u*256;
        int lr = oi >> 7, col = oi & 127;
        int r = r0 + lr;
        if (r < M) {
            float acc = bias[col];
            #pragma unroll
            for (int k=0;k<32;k++) acc = fmaf(sA[lr*32+k], sW[k*128+col], acc);
            int bb = r / Lq, q = r % Lq;
            if (pos) acc += pos[(size_t)(1+q)*128 + col];
            out[((size_t)bb*Tper + 1 + q)*128 + col] = acc;
        }
    }
}

// ---------------- cls token rows ----------------
__global__ void fill_cls(const float* __restrict__ cls_emb, const float* __restrict__ pos)
{
    int b = blockIdx.x, j = threadIdx.x;
    g_Xh [(size_t)b*NT1*128 + j] = cls_emb[j];
    g_Xh2[(size_t)b*NT2*128 + j] = cls_emb[j] + pos[j];
}

// ---------------- transformer-block attention (flash style) ----------------
__global__ void tattn_kernel(const float* __restrict__ Qt, const float* __restrict__ Kt,
                             const float* __restrict__ Vt, float* __restrict__ AO, int T)
{
    const int bh = blockIdx.y, b = bh >> 1, h = bh & 1;
    const int tid = threadIdx.x, lane = tid & 31, warp = tid >> 5;
    const int qi = blockIdx.x*64 + warp*16 + (lane & 15);
    const int half = lane >> 4;
    __shared__ float sK[2][32][64];
    __shared__ float sV[2][32][64];

    float4 qreg[16];
    if (qi < T) {
        const float* qp = Qt + ((size_t)b*T + qi)*128 + h*64;
        #pragma unroll
        for (int i=0;i<16;i++) qreg[i] = *(const float4*)(qp + i*4);
    } else {
        #pragma unroll
        for (int i=0;i<16;i++) qreg[i] = make_float4(0.f,0.f,0.f,0.f);
    }
    float m = -1e30f, l = 0.f;
    float o[64];
    #pragma unroll
    for (int d=0;d<64;d++) o[d]=0.f;

    const int half0 = (T + 1) >> 1;
    const int kbase = half ? half0 : 0;
    const int kend  = half ? T : half0;
    const int hl1 = T - half0;
    const int nch = (((half0 > hl1) ? half0 : hl1) + 31) >> 5;

    for (int c=0;c<nch;c++) {
        __syncthreads();
        #pragma unroll
        for (int u=0;u<16;u++) {
            int e = (tid*16 + u)*4;              // 0..8191
            int isV = e >> 12;
            int e2 = e & 4095;
            int hh = e2 >> 11, kk = (e2 >> 6) & 31, d = e2 & 63;
            int kglob = (hh ? half0 : 0) + c*32 + kk;
            int lim = hh ? T : half0;
            float4 v = make_float4(0.f,0.f,0.f,0.f);
            if (kglob < lim) {
                const float* src = (isV ? Vt : Kt) + ((size_t)b*T + kglob)*128 + h*64 + d;
                v = *(const float4*)src;
            }
            float* dst = isV ? &sV[hh][kk][d] : &sK[hh][kk][d];
            *(float4*)dst = v;
        }
        __syncthreads();
        const int k0 = kbase + c*32;
        for (int kk=0;kk<32;kk++) {
            const float4* kr = (const float4*)sK[half][kk];
            float4 a4 = make_float4(0.f,0.f,0.f,0.f);
            #pragma unroll
            for (int i=0;i<16;i++) {
                float4 kv = kr[i];
                a4.x = fmaf(kv.x, qreg[i].x, a4.x);
                a4.y = fmaf(kv.y, qreg[i].y, a4.y);
                a4.z = fmaf(kv.z, qreg[i].z, a4.z);
                a4.w = fmaf(kv.w, qreg[i].w, a4.w);
            }
            float s = ((a4.x+a4.y)+(a4.z+a4.w))*0.125f;
            if (k0 + kk < kend) {
                if (s > m) {
                    float f = __expf(m - s);
                    l *= f;
                    #pragma unroll
                    for (int d=0;d<64;d++) o[d]*=f;
                    m = s;
                }
                float e = __expf(s - m);
                l += e;
                const float4* vr = (const float4*)sV[half][kk];
                #pragma unroll
                for (int i=0;i<16;i++) {
                    float4 vv = vr[i];
                    o[i*4+0] = fmaf(e, vv.x, o[i*4+0]);
                    o[i*4+1] = fmaf(e, vv.y, o[i*4+1]);
                    o[i*4+2] = fmaf(e, vv.z, o[i*4+2]);
                    o[i*4+3] = fmaf(e, vv.w, o[i*4+3]);
                }
            }
        }
    }
    // merge halves
    float m2 = __shfl_xor_sync(0xffffffffu, m, 16);
    float Mx = fmaxf(m, m2);
    float f1 = __expf(m - Mx), f2 = __expf(m2 - Mx);
    float l2 = __shfl_xor_sync(0xffffffffu, l, 16);
    l = l*f1 + l2*f2;
    #pragma unroll
    for (int d=0;d<64;d++) {
        float o2 = __shfl_xor_sync(0xffffffffu, o[d], 16);
        o[d] = o[d]*f1 + o2*f2;
    }
    if (half == 0 && qi < T) {
        float inv = 1.0f / l;
        float* dst = AO + ((size_t)b*T + qi)*128 + h*64;
        #pragma unroll
        for (int i=0;i<16;i++)
            *(float4*)(dst + i*4) = make_float4(o[i*4]*inv, o[i*4+1]*inv, o[i*4+2]*inv, o[i*4+3]*inv);
    }
}

// ---------------- add + LayerNorm ----------------
__device__ __forceinline__ void addln_row(const float* X, const float* O,
                                          const float* g, const float* bb,
                                          float* dst, size_t rowOff, int j)
{
    float v = X[rowOff + j] + O[rowOff + j];
    float s = v, s2 = v*v;
    #pragma unroll
    for (int off=16; off>0; off>>=1) {
        s  += __shfl_xor_sync(0xffffffffu, s,  off);
        s2 += __shfl_xor_sync(0xffffffffu, s2, off);
    }
    __shared__ float r1[4], r2[4];
    int w = j >> 5;
    if ((j & 31) == 0) { r1[w]=s; r2[w]=s2; }
    __syncthreads();
    s  = r1[0]+r1[1]+r1[2]+r1[3];
    s2 = r2[0]+r2[1]+r2[2]+r2[3];
    float mean = s * (1.f/128.f);
    float var  = s2 * (1.f/128.f) - mean*mean;
    float rs   = rsqrtf(var + 1e-5f);
    dst[j] = (v - mean)*rs*g[j] + bb[j];
}

__global__ void addln_kernel(const float* __restrict__ X, const float* __restrict__ O,
                             const float* __restrict__ g, const float* __restrict__ bb,
                             float* __restrict__ out)
{
    size_t rowOff = (size_t)blockIdx.x * 128;
    addln_row(X, O, g, bb, out + rowOff, rowOff, threadIdx.x);
}

// final LN of the T=513 block: drop cls token, write last_hidden directly
__global__ void addln_final_kernel(const float* __restrict__ X, const float* __restrict__ O,
                                   const float* __restrict__ g, const float* __restrict__ bb,
                                   float* __restrict__ dout)
{
    int row = blockIdx.x;
    int b = row / NT2, t = row % NT2;
    if (t == 0) return;
    size_t rowOff = (size_t)row * 128;
    float* dst = dout + ((size_t)b*NL + (t-1))*128;
    addln_row(X, O, g, bb, dst, rowOff, threadIdx.x);
}

// ---------------- cls pooling ----------------
__global__ void pool_kernel(const float* __restrict__ H, const float* __restrict__ pW,
                            const float* __restrict__ pb, float* __restrict__ dout)
{
    int b = blockIdx.x, j = threadIdx.x;
    __shared__ float s[128];
    s[j] = H[(size_t)b*NT1*128 + j];
    __syncthreads();
    float acc = pb[j];
    #pragma unroll
    for (int k=0;k<128;k++) acc = fmaf(s[k], pW[k*128 + j], acc);
    dout[b*128 + j] = tanhf(acc);
}

// ---------------- launch ----------------
extern "C" void kernel_launch(void* const* d_in, const int* in_sizes, int n_in,
                              void* d_out, int out_size)
{
    (void)in_sizes; (void)n_in; (void)out_size;
    const float* x       = (const float*)d_in[0];
    const float* ts      = (const float*)d_in[1];
    const float* w_per   = (const float*)d_in[2];
    const float* b_per   = (const float*)d_in[3];
    const float* w_lin   = (const float*)d_in[4];
    const float* b_lin   = (const float*)d_in[5];
    const float* Wq_t    = (const float*)d_in[6];
    const float* bq_t    = (const float*)d_in[7];
    const float* Wk_t    = (const float*)d_in[8];
    const float* bk_t    = (const float*)d_in[9];
    const float* Wo_t    = (const float*)d_in[10];
    const float* bo_t    = (const float*)d_in[11];
    const float* pos_emb = (const float*)d_in[12];
    const float* cls_emb = (const float*)d_in[13];
    const float* tWq = (const float*)d_in[14];
    const float* tbq = (const float*)d_in[15];
    const float* tWk = (const float*)d_in[16];
    const float* tbk = (const float*)d_in[17];
    const float* tWv = (const float*)d_in[18];
    const float* tbv = (const float*)d_in[19];
    const float* tWo = (const float*)d_in[20];
    const float* tbo = (const float*)d_in[21];
    const float* ln1_g = (const float*)d_in[22];
    const float* ln1_b = (const float*)d_in[23];
    const float* fW1 = (const float*)d_in[24];
    const float* fb1 = (const float*)d_in[25];
    const float* fW2 = (const float*)d_in[26];
    const float* fb2 = (const float*)d_in[27];
    const float* ln2_g = (const float*)d_in[28];
    const float* ln2_b = (const float*)d_in[29];
    const float* pW  = (const float*)d_in[30];
    const float* pb  = (const float*)d_in[31];
    float* dout = (float*)d_out;

    float *key_e, *clsq, *Qb, *Kb, *Qc, *o32a, *o32c, *Xh, *Xh2, *bq, *bk, *bv, *bao, *bx2, *hout;
    cudaGetSymbolAddress((void**)&key_e, g_key_e);
    cudaGetSymbolAddress((void**)&clsq,  g_clsq);
    cudaGetSymbolAddress((void**)&Qb,    g_Qb);
    cudaGetSymbolAddress((void**)&Kb,    g_Kb);
    cudaGetSymbolAddress((void**)&Qc,    g_Qc);
    cudaGetSymbolAddress((void**)&o32a,  g_o32a);
    cudaGetSymbolAddress((void**)&o32c,  g_o32c);
    cudaGetSymbolAddress((void**)&Xh,    g_Xh);
    cudaGetSymbolAddress((void**)&Xh2,   g_Xh2);
    cudaGetSymbolAddress((void**)&bq,    g_bq);
    cudaGetSymbolAddress((void**)&bk,    g_bk);
    cudaGetSymbolAddress((void**)&bv,    g_bv);
    cudaGetSymbolAddress((void**)&bao,   g_bao);
    cudaGetSymbolAddress((void**)&bx2,   g_bx2);
    cudaGetSymbolAddress((void**)&hout,  g_hout);

    // 1. time embeddings (key_e rows + 128 cls rows)
    emb_kernel<<<NB*NL + 128, 128>>>(ts, w_per, b_per, w_lin, b_lin);

    // 2. K/Q projections of the embeddings
    dim3 gKQ((NB*NL + 63)/64, 2);
    gemm128_kernel<<<gKQ, 256>>>(key_e, Wk_t, bk_t, Kb, NB*NL, 0);
    gemm128_kernel<<<gKQ, 256>>>(key_e, Wq_t, bq_t, Qb, NB*NL, 0);
    gemm128_kernel<<<dim3(2,2), 256>>>(clsq, Wq_t, bq_t, Qc, 128, 0);

    // 3. masked channel attention (out path Lq=512; cls path Lq=128, q broadcast)
    mta_kernel<<<dim3(NL/64, NB*2), 128>>>(Qb, NL*128, NL, Kb, x, o32a);
    mta_kernel<<<dim3(128/64, NB*2), 128>>>(Qc, 0, 128, Kb, x, o32c);

    // 4. build tblock inputs
    fill_cls<<<NB, 128>>>(cls_emb, pos_emb);
    proj32_kernel<<<(NB*NL + 31)/32, 256>>>(o32a, Wo_t, bo_t, Xh2, NB*NL, NL, NT2, pos_emb);
    proj32_kernel<<<(NB*128 + 31)/32, 256>>>(o32c, Wo_t, bo_t, Xh, NB*128, 128, NT1, nullptr);

    // 5. tblock on h (T=129)
    const int M1 = NB*NT1;
    dim3 gh((M1 + 63)/64, 2);
    gemm128_kernel<<<gh, 256>>>(Xh, tWq, tbq, bq, M1, 0);
    gemm128_kernel<<<gh, 256>>>(Xh, tWk, tbk, bk, M1, 0);
    gemm128_kernel<<<gh, 256>>>(Xh, tWv, tbv, bv, M1, 0);
    tattn_kernel<<<dim3((NT1 + 63)/64, NB*2), 128>>>(bq, bk, bv, bao, NT1);
    gemm128_kernel<<<gh, 256>>>(bao, tWo, tbo, bq, M1, 0);
    addln_kernel<<<M1, 128>>>(Xh, bq, ln1_g, ln1_b, bx2);
    gemm128_kernel<<<gh, 256>>>(bx2, fW1, fb1, bk, M1, 1);
    gemm128_kernel<<<gh, 256>>>(bk, fW2, fb2, bv, M1, 0);
    addln_kernel<<<M1, 128>>>(bx2, bv, ln2_g, ln2_b, hout);

    // 6. cls pooling -> dout[0:1024]
    pool_kernel<<<NB, 128>>>(hout, pW, pb, dout);

    // 7. tblock on h2 (T=513), final LN writes last_hidden directly
    const int M2 = NB*NT2;
    dim3 gh2((M2 + 63)/64, 2);
    gemm128_kernel<<<gh2, 256>>>(Xh2, tWq, tbq, bq, M2, 0);
    gemm128_kernel<<<gh2, 256>>>(Xh2, tWk, tbk, bk, M2, 0);
    gemm128_kernel<<<gh2, 256>>>(Xh2, tWv, tbv, bv, M2, 0);
    tattn_kernel<<<dim3((NT2 + 63)/64, NB*2), 128>>>(bq, bk, bv, bao, NT2);
    gemm128_kernel<<<gh2, 256>>>(bao, tWo, tbo, bq, M2, 0);
    addln_kernel<<<M2, 128>>>(Xh2, bq, ln1_g, ln1_b, bx2);
    gemm128_kernel<<<gh2, 256>>>(bx2, fW1, fb1, bk, M2, 1);
    gemm128_kernel<<<gh2, 256>>>(bk, fW2, fb2, bv, M2, 0);
    addln_final_kernel<<<M2, 128>>>(bx2, bv, ln2_g, ln2_b, dout + 1024);
}

// round 2
// speedup vs baseline: 1.2940x; 1.2940x over previous
#include <cuda_runtime.h>
#include <math.h>

#define NB 8
#define NL 512
#define NE 128
#define NT1 129
#define NT2 513
#define M1R (NB*NT1)        // 1032
#define M2R (NB*NT2)        // 4104
#define MTR (M1R+M2R)       // 5136

// ---------------- device scratch ----------------
__device__ float g_key_e[NB*NL*NE];
__device__ float g_clsq [128*NE];
__device__ float g_Qb   [NB*NL*NE];
__device__ float g_Kb   [NB*NL*NE];
__device__ float g_Qc   [128*NE];
__device__ float g_o32a [NB*NL*32];
__device__ float g_o32c [NB*128*32];
__device__ float g_X    [MTR*128];   // merged tblock input (h rows then h2 rows)
__device__ float g_Q    [MTR*128];
__device__ float g_K    [MTR*128];
__device__ float g_V    [MTR*128];
__device__ float g_AO   [MTR*128];
__device__ float g_X2   [MTR*128];   // post-LN1
__device__ float g_F    [MTR*128];   // relu(ffn1)
__device__ float g_hout [M1R*128];

// ---------------- time embedding ----------------
__global__ void emb_kernel(const float* __restrict__ ts,
                           const float* __restrict__ w_per, const float* __restrict__ b_per,
                           const float* __restrict__ w_lin, const float* __restrict__ b_lin)
{
    int row = blockIdx.x, j = threadIdx.x;
    float t; float* dst;
    if (row < NB*NL) { t = ts[row]; dst = g_key_e + (size_t)row*NE; }
    else             { int i = row - NB*NL; t = (float)i * (1.0f/127.0f); dst = g_clsq + (size_t)i*NE; }
    float v;
    if (j == 0) v = t*w_lin[0] + b_lin[0];
    else        v = sinf(t*w_per[j-1] + b_per[j-1]);
    dst[j] = v;
}

// ---------------- 64x64-tile SGEMM body (K=N=128) ----------------
__device__ __forceinline__ void gemm64x64(const float* __restrict__ A, const float* __restrict__ W,
                                          const float* __restrict__ bias, float* __restrict__ C,
                                          int M, int relu)
{
    __shared__ float As[16][64];
    __shared__ float Ws[16][64];
    const int tid = threadIdx.x;            // 256 threads
    const int tn = tid & 15, tm = tid >> 4;
    const int m0 = blockIdx.x * 64, n0 = blockIdx.y * 64;
    float acc[4][4];
    #pragma unroll
    for (int i=0;i<4;i++)
        #pragma unroll
        for (int j=0;j<4;j++) acc[i][j] = 0.f;

    const int la  = tid * 4;
    const int lar = la >> 4, lac = la & 15;   // A tile: 64 rows x 16 cols
    const int lwr = la >> 6, lwc = la & 63;   // W tile: 16 rows x 64 cols

    for (int kk = 0; kk < 128; kk += 16) {
        float4 av = make_float4(0.f,0.f,0.f,0.f);
        int gm = m0 + lar;
        if (gm < M) av = *(const float4*)(A + (size_t)gm*128 + kk + lac);
        float4 wv = *(const float4*)(W + (size_t)(kk+lwr)*128 + n0 + lwc);
        __syncthreads();
        As[lac+0][lar]=av.x; As[lac+1][lar]=av.y; As[lac+2][lar]=av.z; As[lac+3][lar]=av.w;
        *(float4*)&Ws[lwr][lwc] = wv;
        __syncthreads();
        #pragma unroll
        for (int k=0;k<16;k++) {
            float a[4], b[4];
            *(float4*)a = *(const float4*)&As[k][tm*4];
            *(float4*)b = *(const float4*)&Ws[k][tn*4];
            #pragma unroll
            for (int i=0;i<4;i++)
                #pragma unroll
                for (int j=0;j<4;j++) acc[i][j] = fmaf(a[i], b[j], acc[i][j]);
        }
    }
    float4 bv4 = *(const float4*)(bias + n0 + tn*4);
    float bb[4] = {bv4.x, bv4.y, bv4.z, bv4.w};
    #pragma unroll
    for (int i=0;i<4;i++) {
        int gm = m0 + tm*4 + i;
        if (gm < M) {
            float4 o;
            o.x = acc[i][0]+bb[0]; o.y = acc[i][1]+bb[1];
            o.z = acc[i][2]+bb[2]; o.w = acc[i][3]+bb[3];
            if (relu) { o.x=fmaxf(o.x,0.f); o.y=fmaxf(o.y,0.f); o.z=fmaxf(o.z,0.f); o.w=fmaxf(o.w,0.f); }
            *(float4*)(C + (size_t)gm*128 + n0 + tn*4) = o;
        }
    }
}

// K/Q projections of embeddings (z=0: Kb, z=1: Qb, z=2: Qc)
__global__ void kq_gemm_kernel(const float* __restrict__ Wq, const float* __restrict__ bq,
                               const float* __restrict__ Wk, const float* __restrict__ bk)
{
    const float *A, *W, *bias; float* C; int M;
    if (blockIdx.z == 0)      { A=g_key_e; W=Wk; bias=bk; C=g_Kb; M=NB*NL; }
    else if (blockIdx.z == 1) { A=g_key_e; W=Wq; bias=bq; C=g_Qb; M=NB*NL; }
    else                      { A=g_clsq;  W=Wq; bias=bq; C=g_Qc; M=128;  }
    if (blockIdx.x*64 >= M) return;
    gemm64x64(A, W, bias, C, M, 0);
}

// QKV for merged tblock rows (z selects q/k/v)
__global__ void qkv_gemm_kernel(const float* __restrict__ Wq, const float* __restrict__ bq,
                                const float* __restrict__ Wk, const float* __restrict__ bk,
                                const float* __restrict__ Wv, const float* __restrict__ bv)
{
    const float *W, *bias; float* C;
    if (blockIdx.z == 0)      { W=Wq; bias=bq; C=g_Q; }
    else if (blockIdx.z == 1) { W=Wk; bias=bk; C=g_K; }
    else                      { W=Wv; bias=bv; C=g_V; }
    gemm64x64(g_X, W, bias, C, MTR, 0);
}

// plain gemm (used for ffn1 with relu)
__global__ void gemm_kernel(const float* __restrict__ A, const float* __restrict__ W,
                            const float* __restrict__ bias, float* __restrict__ C,
                            int M, int relu)
{
    gemm64x64(A, W, bias, C, M, relu);
}

// ---------------- GEMM (32x128 tile) + bias + residual + LayerNorm ----------------
// mode 0: write to `out` (row-contiguous).  mode 1: final LN → hout (T1 rows) / dlast (T2 rows, skip cls)
__global__ void gemm_ln_kernel(const float* __restrict__ A, const float* __restrict__ W,
                               const float* __restrict__ bias, const float* __restrict__ Res,
                               const float* __restrict__ lng, const float* __restrict__ lnb,
                               float* __restrict__ out, float* __restrict__ dlast,
                               float* __restrict__ hout, int mode)
{
    __shared__ float As[16][32];
    __shared__ float Ws[16][128];
    const int tid = threadIdx.x;          // 256 threads
    const int tn = tid & 31, tm = tid >> 5;
    const int m0 = blockIdx.x * 32;
    float acc[4][4];
    #pragma unroll
    for (int i=0;i<4;i++)
        #pragma unroll
        for (int j=0;j<4;j++) acc[i][j] = 0.f;

    const int lam = tid & 31, lak = (tid >> 5) * 2;   // A: 32 rows x 16 k (float2/thread)

    for (int kk = 0; kk < 128; kk += 16) {
        float2 av = make_float2(0.f,0.f);
        int gm = m0 + lam;
        if (gm < MTR) av = *(const float2*)(A + (size_t)gm*128 + kk + lak);
        float4 wv0, wv1;
        {
            int i0 = tid*4;
            wv0 = *(const float4*)(W + (size_t)(kk + (i0>>7))*128 + (i0&127));
            int i1 = tid*4 + 1024;
            wv1 = *(const float4*)(W + (size_t)(kk + (i1>>7))*128 + (i1&127));
        }
        __syncthreads();
        As[lak][lam] = av.x; As[lak+1][lam] = av.y;
        { int i0 = tid*4;        *(float4*)&Ws[i0>>7][i0&127] = wv0; }
        { int i1 = tid*4 + 1024; *(float4*)&Ws[i1>>7][i1&127] = wv1; }
        __syncthreads();
        #pragma unroll
        for (int k=0;k<16;k++) {
            float a[4], b[4];
            *(float4*)a = *(const float4*)&As[k][tm*4];
            *(float4*)b = *(const float4*)&Ws[k][tn*4];
            #pragma unroll
            for (int i=0;i<4;i++)
                #pragma unroll
                for (int j=0;j<4;j++) acc[i][j] = fmaf(a[i], b[j], acc[i][j]);
        }
    }

    float4 bb4 = *(const float4*)(bias + tn*4);
    float bb[4] = {bb4.x, bb4.y, bb4.z, bb4.w};
    float4 g4 = *(const float4*)(lng + tn*4);
    float4 be4 = *(const float4*)(lnb + tn*4);
    float gg[4] = {g4.x, g4.y, g4.z, g4.w};
    float lb[4] = {be4.x, be4.y, be4.z, be4.w};

    #pragma unroll
    for (int i=0;i<4;i++) {
        int r = m0 + tm*4 + i;          // warp-uniform validity
        if (r >= MTR) continue;
        float4 rv = *(const float4*)(Res + (size_t)r*128 + tn*4);
        float v[4];
        v[0] = acc[i][0] + bb[0] + rv.x;
        v[1] = acc[i][1] + bb[1] + rv.y;
        v[2] = acc[i][2] + bb[2] + rv.z;
        v[3] = acc[i][3] + bb[3] + rv.w;
        float s = v[0]+v[1]+v[2]+v[3];
        float s2 = v[0]*v[0]+v[1]*v[1]+v[2]*v[2]+v[3]*v[3];
        #pragma unroll
        for (int off=16; off>0; off>>=1) {
            s  += __shfl_xor_sync(0xffffffffu, s,  off);
            s2 += __shfl_xor_sync(0xffffffffu, s2, off);
        }
        float mean = s * (1.f/128.f);
        float var  = s2 * (1.f/128.f) - mean*mean;
        float rs   = rsqrtf(var + 1e-5f);
        float4 o;
        o.x = (v[0]-mean)*rs*gg[0] + lb[0];
        o.y = (v[1]-mean)*rs*gg[1] + lb[1];
        o.z = (v[2]-mean)*rs*gg[2] + lb[2];
        o.w = (v[3]-mean)*rs*gg[3] + lb[3];
        if (mode == 0) {
            *(float4*)(out + (size_t)r*128 + tn*4) = o;
        } else {
            if (r < M1R) {
                *(float4*)(hout + (size_t)r*128 + tn*4) = o;
            } else {
                int rr = r - M1R;
                int t  = rr % NT2;
                if (t == 0) continue;
                int b  = rr / NT2;
                *(float4*)(dlast + ((size_t)b*NL + t - 1)*128 + tn*4) = o;
            }
        }
    }
}

// ---------------- masked per-channel attention (mTA), merged main+cls ----------------
__global__ void mta_kernel(const float* __restrict__ Qmain, const float* __restrict__ Qcls,
                           const float* __restrict__ K, const float* __restrict__ X,
                           float* __restrict__ o32main, float* __restrict__ o32cls)
{
    const int bh = blockIdx.y, b = bh >> 1, h = bh & 1;
    const bool cls = blockIdx.x >= 8;
    const int tile = cls ? (blockIdx.x - 8) : blockIdx.x;
    const float* Q = cls ? Qcls : Qmain;
    const int qStride = cls ? 0 : NL*128;
    const int Lq = cls ? 128 : NL;
    float* o32 = cls ? o32cls : o32main;

    const int tid = threadIdx.x, lane = tid & 31, warp = tid >> 5;
    const int qi = tile*64 + warp*16 + (lane & 15);
    const int half = lane >> 4;
    __shared__ float sK[2][32][64];
    __shared__ float sX[2][32][16];

    float4 qreg[16];
    const float* qp = Q + (size_t)b*qStride + (size_t)qi*128 + h*64;
    #pragma unroll
    for (int i=0;i<16;i++) qreg[i] = *(const float4*)(qp + i*4);

    float m = -1e30f;
    float den[8], num[8];
    #pragma unroll
    for (int c=0;c<8;c++){ den[c]=0.f; num[c]=0.f; }

    for (int c=0;c<8;c++) {             // 8 chunks of 32 keys per half
        __syncthreads();
        #pragma unroll
        for (int u=0;u<8;u++) {
            int e = (tid*8+u)*4;
            int hh = e>>11, kk = (e>>6)&31, d = e&63;
            int kglob = hh*256 + c*32 + kk;
            *(float4*)&sK[hh][kk][d] =
                *(const float4*)(K + ((size_t)b*NL + kglob)*128 + h*64 + d);
        }
        #pragma unroll
        for (int u=0;u<2;u++) {
            int e = (tid*2+u)*4;
            int hh = e>>9, kk = (e>>4)&31, d = e&15;
            int kglob = hh*256 + c*32 + kk;
            *(float4*)&sX[hh][kk][d] =
                *(const float4*)(X + ((size_t)b*NL + kglob)*16 + d);
        }
        __syncthreads();
        for (int kk=0;kk<32;kk++) {
            const float4* kr = (const float4*)sK[half][kk];
            float4 a4 = make_float4(0.f,0.f,0.f,0.f);
            #pragma unroll
            for (int i=0;i<16;i++) {
                float4 kv = kr[i];
                a4.x = fmaf(kv.x, qreg[i].x, a4.x);
                a4.y = fmaf(kv.y, qreg[i].y, a4.y);
                a4.z = fmaf(kv.z, qreg[i].z, a4.z);
                a4.w = fmaf(kv.w, qreg[i].w, a4.w);
            }
            float s = ((a4.x+a4.y)+(a4.z+a4.w))*0.125f;
            if (s > m) {
                float f = __expf(m - s);
                #pragma unroll
                for (int cc=0;cc<8;cc++){ den[cc]*=f; num[cc]*=f; }
                m = s;
            }
            float e = __expf(s - m);
            const float* xr = sX[half][kk];
            #pragma unroll
            for (int cc=0;cc<8;cc++) {
                float t = e * xr[8+cc];
                den[cc] += t;
                num[cc] = fmaf(t, xr[cc], num[cc]);
            }
        }
    }
    float m2 = __shfl_xor_sync(0xffffffffu, m, 16);
    float Mx = fmaxf(m, m2);
    float f1 = __expf(m - Mx), f2 = __expf(m2 - Mx);
    #pragma unroll
    for (int cc=0;cc<8;cc++) {
        float d2 = __shfl_xor_sync(0xffffffffu, den[cc], 16);
        float n2 = __shfl_xor_sync(0xffffffffu, num[cc], 16);
        den[cc] = den[cc]*f1 + d2*f2;
        num[cc] = num[cc]*f1 + n2*f2;
    }
    if (half == 0) {
        float res[16];
        #pragma unroll
        for (int cc=0;cc<8;cc++) {
            bool ok = den[cc] > 0.f;
            res[cc]   = ok ? num[cc]/den[cc] : 0.f;
            res[8+cc] = ok ? 1.f : 0.f;
        }
        float* dst = o32 + ((size_t)b*Lq + qi)*32 + h*16;
        #pragma unroll
        for (int i=0;i<4;i++)
            *(float4*)(dst + i*4) = make_float4(res[i*4],res[i*4+1],res[i*4+2],res[i*4+3]);
    }
}

// ---------------- 32->128 projection into merged X (main + cls paths) ----------------
__global__ void proj32_kernel(const float* __restrict__ Am, const float* __restrict__ Ac,
                              const float* __restrict__ W, const float* __restrict__ bias,
                              const float* __restrict__ pos)
{
    __shared__ float sW[32*128];
    __shared__ float sA[32*32];
    const bool cls = blockIdx.x >= 128;
    const float* A = cls ? Ac : Am;
    const int Lq = cls ? 128 : NL;
    const int r0 = (cls ? (blockIdx.x - 128) : blockIdx.x) * 32;
    for (int i = threadIdx.x; i < 4096; i += 256) sW[i] = W[i];
    for (int i = threadIdx.x; i < 1024; i += 256)
        sA[i] = A[(size_t)(r0 + (i >> 5))*32 + (i & 31)];
    __syncthreads();
    #pragma unroll
    for (int u=0;u<16;u++) {
        int oi = threadIdx.x + u*256;
        int lr = oi >> 7, col = oi & 127;
        int r = r0 + lr;
        float acc = bias[col];
        #pragma unroll
        for (int k=0;k<32;k++) acc = fmaf(sA[lr*32+k], sW[k*128+col], acc);
        int bb = r / Lq, q = r % Lq;
        size_t row;
        if (cls) row = (size_t)bb*NT1 + 1 + q;
        else   { row = (size_t)M1R + (size_t)bb*NT2 + 1 + q; acc += pos[(size_t)(1+q)*128 + col]; }
        g_X[row*128 + col] = acc;
    }
}

// ---------------- cls token rows ----------------
__global__ void fill_cls(const float* __restrict__ cls_emb, const float* __restrict__ pos)
{
    int b = blockIdx.x, j = threadIdx.x;
    g_X[((size_t)b*NT1)*128 + j] = cls_emb[j];
    g_X[((size_t)M1R + (size_t)b*NT2)*128 + j] = cls_emb[j] + pos[j];
}

// ---------------- transformer-block attention (flash style), merged T1+T2 ----------------
__global__ void tattn_kernel()
{
    const int y = blockIdx.y;
    const int part = y >> 4;              // 0: T1 block, 1: T2 block
    const int bh = y & 15, b = bh >> 1, h = bh & 1;
    const int T = part ? NT2 : NT1;
    const int base = part ? (M1R + b*NT2) : (b*NT1);
    if (blockIdx.x * 64 >= T) return;

    const int tid = threadIdx.x, lane = tid & 31, warp = tid >> 5;
    const int qi = blockIdx.x*64 + warp*16 + (lane & 15);
    const int half = lane >> 4;
    __shared__ float sK[2][32][64];
    __shared__ float sV[2][32][64];

    float4 qreg[16];
    if (qi < T) {
        const float* qp = g_Q + ((size_t)base + qi)*128 + h*64;
        #pragma unroll
        for (int i=0;i<16;i++) qreg[i] = *(const float4*)(qp + i*4);
    } else {
        #pragma unroll
        for (int i=0;i<16;i++) qreg[i] = make_float4(0.f,0.f,0.f,0.f);
    }
    float m = -1e30f, l = 0.f;
    float o[64];
    #pragma unroll
    for (int d=0;d<64;d++) o[d]=0.f;

    const int half0 = (T + 1) >> 1;
    const int kbase = half ? half0 : 0;
    const int kend  = half ? T : half0;
    const int hl1 = T - half0;
    const int nch = (((half0 > hl1) ? half0 : hl1) + 31) >> 5;

    for (int c=0;c<nch;c++) {
        __syncthreads();
        #pragma unroll
        for (int u=0;u<16;u++) {
            int e = (tid*16 + u)*4;
            int isV = e >> 12;
            int e2 = e & 4095;
            int hh = e2 >> 11, kk = (e2 >> 6) & 31, d = e2 & 63;
            int kglob = (hh ? half0 : 0) + c*32 + kk;
            int lim = hh ? T : half0;
            float4 v = make_float4(0.f,0.f,0.f,0.f);
            if (kglob < lim) {
                const float* src = (isV ? g_V : g_K) + ((size_t)base + kglob)*128 + h*64 + d;
                v = *(const float4*)src;
            }
            float* dst = isV ? &sV[hh][kk][d] : &sK[hh][kk][d];
            *(float4*)dst = v;
        }
        __syncthreads();
        const int k0 = kbase + c*32;
        for (int kk=0;kk<32;kk++) {
            const float4* kr = (const float4*)sK[half][kk];
            float4 a4 = make_float4(0.f,0.f,0.f,0.f);
            #pragma unroll
            for (int i=0;i<16;i++) {
                float4 kv = kr[i];
                a4.x = fmaf(kv.x, qreg[i].x, a4.x);
                a4.y = fmaf(kv.y, qreg[i].y, a4.y);
                a4.z = fmaf(kv.z, qreg[i].z, a4.z);
                a4.w = fmaf(kv.w, qreg[i].w, a4.w);
            }
            float s = ((a4.x+a4.y)+(a4.z+a4.w))*0.125f;
            if (k0 + kk < kend) {
                if (s > m) {
                    float f = __expf(m - s);
                    l *= f;
                    #pragma unroll
                    for (int d=0;d<64;d++) o[d]*=f;
                    m = s;
                }
                float e = __expf(s - m);
                l += e;
                const float4* vr = (const float4*)sV[half][kk];
                #pragma unroll
                for (int i=0;i<16;i++) {
                    float4 vv = vr[i];
                    o[i*4+0] = fmaf(e, vv.x, o[i*4+0]);
                    o[i*4+1] = fmaf(e, vv.y, o[i*4+1]);
                    o[i*4+2] = fmaf(e, vv.z, o[i*4+2]);
                    o[i*4+3] = fmaf(e, vv.w, o[i*4+3]);
                }
            }
        }
    }
    float m2 = __shfl_xor_sync(0xffffffffu, m, 16);
    float Mx = fmaxf(m, m2);
    float f1 = __expf(m - Mx), f2 = __expf(m2 - Mx);
    float l2 = __shfl_xor_sync(0xffffffffu, l, 16);
    l = l*f1 + l2*f2;
    #pragma unroll
    for (int d=0;d<64;d++) {
        float o2 = __shfl_xor_sync(0xffffffffu, o[d], 16);
        o[d] = o[d]*f1 + o2*f2;
    }
    if (half == 0 && qi < T) {
        float inv = 1.0f / l;
        float* dst = g_AO + ((size_t)base + qi)*128 + h*64;
        #pragma unroll
        for (int i=0;i<16;i++)
            *(float4*)(dst + i*4) = make_float4(o[i*4]*inv, o[i*4+1]*inv, o[i*4+2]*inv, o[i*4+3]*inv);
    }
}

// ---------------- cls pooling ----------------
__global__ void pool_kernel(const float* __restrict__ pW,
                            const float* __restrict__ pb, float* __restrict__ dout)
{
    int b = blockIdx.x, j = threadIdx.x;
    __shared__ float s[128];
    s[j] = g_hout[((size_t)b*NT1)*128 + j];
    __syncthreads();
    float acc = pb[j];
    #pragma unroll
    for (int k=0;k<128;k++) acc = fmaf(s[k], pW[k*128 + j], acc);
    dout[b*128 + j] = tanhf(acc);
}

// ---------------- launch ----------------
extern "C" void kernel_launch(void* const* d_in, const int* in_sizes, int n_in,
                              void* d_out, int out_size)
{
    (void)in_sizes; (void)n_in; (void)out_size;
    const float* x       = (const float*)d_in[0];
    const float* ts      = (const float*)d_in[1];
    const float* w_per   = (const float*)d_in[2];
    const float* b_per   = (const float*)d_in[3];
    const float* w_lin   = (const float*)d_in[4];
    const float* b_lin   = (const float*)d_in[5];
    const float* Wq_t    = (const float*)d_in[6];
    const float* bq_t    = (const float*)d_in[7];
    const float* Wk_t    = (const float*)d_in[8];
    const float* bk_t    = (const float*)d_in[9];
    const float* Wo_t    = (const float*)d_in[10];
    const float* bo_t    = (const float*)d_in[11];
    const float* pos_emb = (const float*)d_in[12];
    const float* cls_emb = (const float*)d_in[13];
    const float* tWq = (const float*)d_in[14];
    const float* tbq = (const float*)d_in[15];
    const float* tWk = (const float*)d_in[16];
    const float* tbk = (const float*)d_in[17];
    const float* tWv = (const float*)d_in[18];
    const float* tbv = (const float*)d_in[19];
    const float* tWo = (const float*)d_in[20];
    const float* tbo = (const float*)d_in[21];
    const float* ln1_g = (const float*)d_in[22];
    const float* ln1_b = (const float*)d_in[23];
    const float* fW1 = (const float*)d_in[24];
    const float* fb1 = (const float*)d_in[25];
    const float* fW2 = (const float*)d_in[26];
    const float* fb2 = (const float*)d_in[27];
    const float* ln2_g = (const float*)d_in[28];
    const float* ln2_b = (const float*)d_in[29];
    const float* pW  = (const float*)d_in[30];
    const float* pb  = (const float*)d_in[31];
    float* dout = (float*)d_out;

    float *Qb, *Kb, *Qc, *o32a, *o32c, *X2, *AO, *F, *hout;
    cudaGetSymbolAddress((void**)&Qb,   g_Qb);
    cudaGetSymbolAddress((void**)&Kb,   g_Kb);
    cudaGetSymbolAddress((void**)&Qc,   g_Qc);
    cudaGetSymbolAddress((void**)&o32a, g_o32a);
    cudaGetSymbolAddress((void**)&o32c, g_o32c);
    cudaGetSymbolAddress((void**)&X2,   g_X2);
    cudaGetSymbolAddress((void**)&AO,   g_AO);
    cudaGetSymbolAddress((void**)&F,    g_F);
    cudaGetSymbolAddress((void**)&hout, g_hout);
    float* Xm; cudaGetSymbolAddress((void**)&Xm, g_X);

    // 1. time embeddings
    emb_kernel<<<NB*NL + 128, 128>>>(ts, w_per, b_per, w_lin, b_lin);

    // 2. K/Q projections (3 GEMMs in one launch)
    kq_gemm_kernel<<<dim3(64, 2, 3), 256>>>(Wq_t, bq_t, Wk_t, bk_t);

    // 3. masked channel attention (main + cls in one launch)
    mta_kernel<<<dim3(10, NB*2), 128>>>(Qb, Qc, Kb, x, o32a, o32c);

    // 4. build merged tblock input
    fill_cls<<<NB, 128>>>(cls_emb, pos_emb);
    proj32_kernel<<<160, 256>>>(o32a, o32c, Wo_t, bo_t, pos_emb);

    // 5. merged tblock (both T=129 and T=513 at once, same weights)
    qkv_gemm_kernel<<<dim3((MTR+63)/64, 2, 3), 256>>>(tWq, tbq, tWk, tbk, tWv, tbv);
    tattn_kernel<<<dim3((NT2+63)/64, 32), 128>>>();
    gemm_ln_kernel<<<(MTR+31)/32, 256>>>(AO, tWo, tbo, Xm, ln1_g, ln1_b, X2, nullptr, nullptr, 0);
    gemm_kernel<<<dim3((MTR+63)/64, 2), 256>>>(X2, fW1, fb1, F, MTR, 1);
    gemm_ln_kernel<<<(MTR+31)/32, 256>>>(F, fW2, fb2, X2, ln2_g, ln2_b, nullptr, dout + 1024, hout, 1);

    // 6. cls pooling -> dout[0:1024]
    pool_kernel<<<NB, 128>>>(pW, pb, dout);
}